// round 7
// baseline (speedup 1.0000x reference)
#include <cuda_runtime.h>

#define N_NEURONS 131072
#define NSTATES   32
#define CDIM      16
#define NBATCH    4
#define X_ELEMS   (NBATCH * N_NEURONS * NSTATES)   // 16777216
#define S_ELEMS   (N_NEURONS * NSTATES)            // 4194304

typedef unsigned long long u64;

// ---------------- f32x2 packed helpers ----------------
__device__ __forceinline__ u64 pack2(float a, float b) {
    u64 r; asm("mov.b64 %0, {%1, %2};" : "=l"(r) : "f"(a), "f"(b)); return r;
}
__device__ __forceinline__ float2 unpack2(u64 v) {
    float2 f; asm("mov.b64 {%0, %1}, %2;" : "=f"(f.x), "=f"(f.y) : "l"(v)); return f;
}
__device__ __forceinline__ u64 fma2(u64 a, u64 b, u64 c) {
    u64 d; asm("fma.rn.f32x2 %0, %1, %2, %3;" : "=l"(d) : "l"(a), "l"(b), "l"(c)); return d;
}
__device__ __forceinline__ u64 mul2(u64 a, u64 b) {
    u64 d; asm("mul.rn.f32x2 %0, %1, %2;" : "=l"(d) : "l"(a), "l"(b)); return d;
}

// ---------------- tanh pieces ----------------
// deg-15 odd Taylor poly of tanh: accurate to ~6e-6 for |x| <= 0.762
__device__ __forceinline__ u64 poly2(u64 x2, const u64* __restrict__ C) {
    u64 t2 = mul2(x2, x2);
    u64 p  = fma2(t2, C[0], C[1]);
    p = fma2(t2, p, C[2]);
    p = fma2(t2, p, C[3]);
    p = fma2(t2, p, C[4]);
    p = fma2(t2, p, C[5]);
    p = fma2(t2, p, C[6]);
    p = fma2(t2, p, C[7]);
    return mul2(p, x2);
}

__device__ __forceinline__ void make_coeffs(u64* C) {
    const float c[8] = { -0.001455834387f,  0.003592128037f, -0.008863235530f,
                          0.021869488537f, -0.053968253968f,  0.133333333333f,
                         -0.333333333333f,  1.0f };
    #pragma unroll
    for (int i = 0; i < 8; i++) C[i] = pack2(c[i], c[i]);
}

__device__ __forceinline__ float mufu_tanh(float x) {
    float t; asm("tanh.approx.f32 %0, %1;" : "=f"(t) : "f"(x)); return t;
}

// stage 1: hybrid MUFU.TANH (|x|>=0.125) / 2-term odd poly (below; rel err <4e-5)
__device__ __forceinline__ void tanh_s1_pair(float& a, float& b) {
    const float xa = a, xb = b;
    float ta = mufu_tanh(xa);
    float tb = mufu_tanh(xb);
    u64 x2 = pack2(xa, xb);
    u64 t2 = mul2(x2, x2);
    u64 p  = fma2(t2, pack2(-0.333333333f, -0.333333333f), pack2(1.0f, 1.0f));
    float2 pp = unpack2(mul2(p, x2));
    a = (fabsf(xa) >= 0.125f) ? ta : pp.x;
    b = (fabsf(xb) >= 0.125f) ? tb : pp.y;
}

// stage 2: branch-free (e^{2y}-1)/(e^{2y}+1); tiny-|y| passthrough select
__device__ __forceinline__ void tanh_s2_pair(float& a, float& b) {
    const float ya = a, yb = b;
    float2 s = unpack2(mul2(pack2(ya, yb), pack2(2.8853900817779268f, 2.8853900817779268f)));
    float ea, eb;
    asm("ex2.approx.ftz.f32 %0, %1;" : "=f"(ea) : "f"(s.x));
    asm("ex2.approx.ftz.f32 %0, %1;" : "=f"(eb) : "f"(s.y));
    float na = ea - 1.0f, da = ea + 1.0f;
    float nb = eb - 1.0f, db = eb + 1.0f;
    float ra, rb;
    asm("rcp.approx.ftz.f32 %0, %1;" : "=f"(ra) : "f"(da));
    asm("rcp.approx.ftz.f32 %0, %1;" : "=f"(rb) : "f"(db));
    float ta = na * ra;
    float tb = nb * rb;
    a = (fabsf(ya) >= 0.01f) ? ta : ya;
    b = (fabsf(yb) >= 0.01f) ? tb : yb;
}

__device__ __forceinline__ void tanh4_pair(float& a, float& b, const u64* __restrict__ C) {
    tanh_s1_pair(a, b);
    tanh_s2_pair(a, b);
    float2 f = unpack2(poly2(pack2(a, b), C)); a = f.x; b = f.y;
    f = unpack2(poly2(pack2(a, b), C));        a = f.x; b = f.y;
}

// =================== tanh kernel: 32 elems/thread ===================
#define TTPB 256
#define TANH_GRID (X_ELEMS / 32 / TTPB)   // 2048 blocks

__global__ void __launch_bounds__(TTPB)
tanh_kernel(const float4* __restrict__ xin, float4* __restrict__ xout)
{
    u64 C[8];
    make_coeffs(C);

    const int base = blockIdx.x * (TTPB * 8) + threadIdx.x;
    #pragma unroll
    for (int half = 0; half < 2; half++) {
        float4 v[4];
        #pragma unroll
        for (int k = 0; k < 4; k++) v[k] = xin[base + (half * 4 + k) * TTPB];
        #pragma unroll
        for (int k = 0; k < 4; k++) {
            tanh4_pair(v[k].x, v[k].y, C);
            tanh4_pair(v[k].z, v[k].w, C);
        }
        #pragma unroll
        for (int k = 0; k < 4; k++) xout[base + (half * 4 + k) * TTPB] = v[k];
    }
}

// =================== states kernel: 2 neurons/thread ===================
#define STPB 128
#define NPT  2

// compare-exchange, descending (hi to lower index)
#define CE(arr, i, j) { float _hi = fmaxf(arr[i], arr[j]); \
                        float _lo = fminf(arr[i], arr[j]); \
                        arr[i] = _hi; arr[j] = _lo; }

__global__ void __launch_bounds__(STPB, 2)
states_kernel(const float* __restrict__ ns,
              const float* __restrict__ Wenc,
              const float* __restrict__ benc,
              const float* __restrict__ Wdec,
              const float* __restrict__ bdec,
              float* __restrict__ sout)
{
    __shared__ __align__(16) float sWenc[CDIM * NSTATES];  // [j][s]
    __shared__ __align__(16) float sWdec[NSTATES * CDIM];  // [s][j]
    __shared__ float sbenc[CDIM];
    __shared__ float sbdec[NSTATES];
    {
        const int t = threadIdx.x;
        for (int i = t; i < CDIM * NSTATES; i += STPB) { sWenc[i] = Wenc[i]; sWdec[i] = Wdec[i]; }
        if (t < CDIM) sbenc[t] = benc[t];
        else if (t >= 64 && t < 64 + NSTATES) sbdec[t - 64] = bdec[t - 64];
    }
    __syncthreads();

    // thread handles neurons n0 and n0 + STPB (both coalesced)
    const int n0 = blockIdx.x * (STPB * NPT) + threadIdx.x;

    float st[NPT][NSTATES];
    float acc[NPT][NSTATES];
    #pragma unroll
    for (int p = 0; p < NPT; p++) {
        const float4* src = reinterpret_cast<const float4*>(ns)
                          + (size_t)(n0 + p * STPB) * (NSTATES / 4);
        #pragma unroll
        for (int i = 0; i < NSTATES / 4; i++) {
            float4 v = src[i];
            st[p][4*i+0] = v.x; st[p][4*i+1] = v.y; st[p][4*i+2] = v.z; st[p][4*i+3] = v.w;
        }
        // layer-0 sparsity mask (no-op for later layers: survivors are 0 or >=0.05)
        #pragma unroll
        for (int s = 0; s < NSTATES; s++) {
            float v = st[p][s];
            st[p][s] = (fabsf(v) >= 0.01f) ? v : 0.0f;
            acc[p][s] = 0.0f;
        }
    }

    #pragma unroll 1
    for (int L = 0; L < 4; L++) {
        // 0.9 decay folded into the recency normalizer
        const float wscl = (L == 0) ? 0.9f
                         : (L == 1) ? (0.9f / 1.7f)
                         : (L == 2) ? (0.9f / 2.19f)
                         :            (0.9f / 2.533f);
        const u64 WSCL2 = pack2(wscl, wscl);

        // recency running sum -> scaled average, packed pairs for the GEMMs
        u64 pst[NPT][NSTATES / 2];
        #pragma unroll
        for (int p = 0; p < NPT; p++) {
            #pragma unroll
            for (int i = 0; i < NSTATES / 2; i++) {
                float a0 = fmaf(acc[p][2*i+0], 0.7f, st[p][2*i+0]);
                float a1 = fmaf(acc[p][2*i+1], 0.7f, st[p][2*i+1]);
                acc[p][2*i+0] = a0; acc[p][2*i+1] = a1;
                pst[p][i] = mul2(pack2(a0, a1), WSCL2);
            }
        }

        // encoder: one weight load feeds both neurons (LDS halved per neuron)
        u64 ph[NPT][CDIM / 2];
        #pragma unroll 2
        for (int j2 = 0; j2 < CDIM / 2; j2++) {
            float hj[NPT][2];
            #pragma unroll
            for (int q = 0; q < 2; q++) {
                const int j = 2 * j2 + q;
                const ulonglong2* w = reinterpret_cast<const ulonglong2*>(&sWenc[j * NSTATES]);
                const u64 bias = pack2(sbenc[j], 0.0f);
                u64 a0 = bias, a1 = bias;
                #pragma unroll
                for (int k = 0; k < 8; k++) {
                    ulonglong2 wv = w[k];
                    a0 = fma2(pst[0][2*k+0], wv.x, a0);
                    a1 = fma2(pst[1][2*k+0], wv.x, a1);
                    a0 = fma2(pst[0][2*k+1], wv.y, a0);
                    a1 = fma2(pst[1][2*k+1], wv.y, a1);
                }
                float2 f0 = unpack2(a0);
                float2 f1 = unpack2(a1);
                hj[0][q] = fmaxf(f0.x + f0.y, 0.0f);
                hj[1][q] = fmaxf(f1.x + f1.y, 0.0f);
            }
            ph[0][j2] = pack2(hj[0][0], hj[0][1]);
            ph[1][j2] = pack2(hj[1][0], hj[1][1]);
        }

        // decoder + importance threshold, shared weight loads
        #pragma unroll 4
        for (int s = 0; s < NSTATES; s++) {
            const ulonglong2* w = reinterpret_cast<const ulonglong2*>(&sWdec[s * CDIM]);
            const u64 bias = pack2(sbdec[s], 0.0f);
            u64 a0 = bias, a1 = bias;
            #pragma unroll
            for (int k = 0; k < 4; k++) {
                ulonglong2 wv = w[k];
                a0 = fma2(ph[0][2*k+0], wv.x, a0);
                a1 = fma2(ph[1][2*k+0], wv.x, a1);
                a0 = fma2(ph[0][2*k+1], wv.y, a0);
                a1 = fma2(ph[1][2*k+1], wv.y, a1);
            }
            float2 f0 = unpack2(a0);
            float2 f1 = unpack2(a1);
            float v0 = f0.x + f0.y;
            float v1 = f1.x + f1.y;
            st[0][s] = (fabsf(v0) >= 0.05f) ? v0 : 0.0f;
            st[1][s] = (fabsf(v1) >= 0.05f) ? v1 : 0.0f;
        }

        // ---- exact 8th-largest of |st| via bitonic selection, per neuron ----
        #pragma unroll
        for (int p = 0; p < NPT; p++) {
            float v[NSTATES];
            #pragma unroll
            for (int i = 0; i < NSTATES; i++) v[i] = fabsf(st[p][i]);

            // Batcher odd-even sort-8 (descending), 19 CE per group of 8
            #pragma unroll
            for (int g = 0; g < 32; g += 8) {
                CE(v, g+0, g+1) CE(v, g+2, g+3) CE(v, g+4, g+5) CE(v, g+6, g+7)
                CE(v, g+0, g+2) CE(v, g+1, g+3) CE(v, g+4, g+6) CE(v, g+5, g+7)
                CE(v, g+1, g+2) CE(v, g+5, g+6)
                CE(v, g+0, g+4) CE(v, g+1, g+5) CE(v, g+2, g+6) CE(v, g+3, g+7)
                CE(v, g+2, g+4) CE(v, g+3, g+5)
                CE(v, g+1, g+2) CE(v, g+3, g+4) CE(v, g+5, g+6)
            }

            // top-8 of G0∪G1 (bitonic split) then sort desc
            float m[8];
            #pragma unroll
            for (int i = 0; i < 8; i++) m[i] = fmaxf(v[i], v[15 - i]);
            CE(m,0,4) CE(m,1,5) CE(m,2,6) CE(m,3,7)
            CE(m,0,2) CE(m,1,3) CE(m,4,6) CE(m,5,7)
            CE(m,0,1) CE(m,2,3) CE(m,4,5) CE(m,6,7)

            // top-8 of G2∪G3, sorted
            float q[8];
            #pragma unroll
            for (int i = 0; i < 8; i++) q[i] = fmaxf(v[16 + i], v[31 - i]);
            CE(q,0,4) CE(q,1,5) CE(q,2,6) CE(q,3,7)
            CE(q,0,2) CE(q,1,3) CE(q,4,6) CE(q,5,7)
            CE(q,0,1) CE(q,2,3) CE(q,4,5) CE(q,6,7)

            // kth = min of top-8 of (m ∪ q) = min_i max(m[i], q[7-i])
            float kth = fmaxf(m[0], q[7]);
            #pragma unroll
            for (int i = 1; i < 8; i++) kth = fminf(kth, fmaxf(m[i], q[7 - i]));

            #pragma unroll
            for (int s = 0; s < NSTATES; s++)
                st[p][s] = (fabsf(st[p][s]) >= kth) ? st[p][s] : 0.0f;
        }
    }

    #pragma unroll
    for (int p = 0; p < NPT; p++) {
        float4* dst = reinterpret_cast<float4*>(sout)
                    + (size_t)(n0 + p * STPB) * (NSTATES / 4);
        #pragma unroll
        for (int i = 0; i < NSTATES / 4; i++) {
            float4 v4;
            v4.x = st[p][4*i+0]; v4.y = st[p][4*i+1];
            v4.z = st[p][4*i+2]; v4.w = st[p][4*i+3];
            dst[i] = v4;
        }
    }
}

extern "C" void kernel_launch(void* const* d_in, const int* in_sizes, int n_in,
                              void* d_out, int out_size) {
    const float* x    = (const float*)d_in[0];
    const float* ns   = (const float*)d_in[1];
    const float* Wenc = (const float*)d_in[2];
    const float* benc = (const float*)d_in[3];
    const float* Wdec = (const float*)d_in[4];
    const float* bdec = (const float*)d_in[5];

    float* out  = (float*)d_out;
    float* xout = nullptr;
    float* sout = nullptr;
    if (out_size >= X_ELEMS + S_ELEMS) { xout = out; sout = out + X_ELEMS; }
    else if (out_size == S_ELEMS)      { sout = out; }
    else                               { xout = out; }

    if (xout)
        tanh_kernel<<<TANH_GRID, TTPB>>>(reinterpret_cast<const float4*>(x),
                                         reinterpret_cast<float4*>(xout));
    if (sout)
        states_kernel<<<N_NEURONS / (STPB * NPT), STPB>>>(ns, Wenc, benc, Wdec, bdec, sout);
}

// round 8
// speedup vs baseline: 1.0316x; 1.0316x over previous
#include <cuda_runtime.h>

#define N_NEURONS 131072
#define NSTATES   32
#define CDIM      16
#define NBATCH    4
#define X_ELEMS   (NBATCH * N_NEURONS * NSTATES)   // 16777216
#define S_ELEMS   (N_NEURONS * NSTATES)            // 4194304

typedef unsigned long long u64;

// ---------------- f32x2 packed helpers ----------------
__device__ __forceinline__ u64 pack2(float a, float b) {
    u64 r; asm("mov.b64 %0, {%1, %2};" : "=l"(r) : "f"(a), "f"(b)); return r;
}
__device__ __forceinline__ float2 unpack2(u64 v) {
    float2 f; asm("mov.b64 {%0, %1}, %2;" : "=f"(f.x), "=f"(f.y) : "l"(v)); return f;
}
__device__ __forceinline__ u64 fma2(u64 a, u64 b, u64 c) {
    u64 d; asm("fma.rn.f32x2 %0, %1, %2, %3;" : "=l"(d) : "l"(a), "l"(b), "l"(c)); return d;
}
__device__ __forceinline__ u64 mul2(u64 a, u64 b) {
    u64 d; asm("mul.rn.f32x2 %0, %1, %2;" : "=l"(d) : "l"(a), "l"(b)); return d;
}

// ---------------- tanh pieces ----------------
// deg-15 odd Taylor poly of tanh: accurate to ~6e-6 for |x| <= 0.762
__device__ __forceinline__ u64 poly2(u64 x2, const u64* __restrict__ C) {
    u64 t2 = mul2(x2, x2);
    u64 p  = fma2(t2, C[0], C[1]);
    p = fma2(t2, p, C[2]);
    p = fma2(t2, p, C[3]);
    p = fma2(t2, p, C[4]);
    p = fma2(t2, p, C[5]);
    p = fma2(t2, p, C[6]);
    p = fma2(t2, p, C[7]);
    return mul2(p, x2);
}

__device__ __forceinline__ void make_coeffs(u64* C) {
    const float c[8] = { -0.001455834387f,  0.003592128037f, -0.008863235530f,
                          0.021869488537f, -0.053968253968f,  0.133333333333f,
                         -0.333333333333f,  1.0f };
    #pragma unroll
    for (int i = 0; i < 8; i++) C[i] = pack2(c[i], c[i]);
}

__device__ __forceinline__ float mufu_tanh(float x) {
    float t; asm("tanh.approx.f32 %0, %1;" : "=f"(t) : "f"(x)); return t;
}

// stage 1: hybrid MUFU.TANH (|x|>=0.125) / 2-term odd poly (below; rel err <4e-5)
__device__ __forceinline__ void tanh_s1_pair(float& a, float& b) {
    const float xa = a, xb = b;
    float ta = mufu_tanh(xa);
    float tb = mufu_tanh(xb);
    u64 x2 = pack2(xa, xb);
    u64 t2 = mul2(x2, x2);
    u64 p  = fma2(t2, pack2(-0.333333333f, -0.333333333f), pack2(1.0f, 1.0f));
    float2 pp = unpack2(mul2(p, x2));
    a = (fabsf(xa) >= 0.125f) ? ta : pp.x;
    b = (fabsf(xb) >= 0.125f) ? tb : pp.y;
}

// stage 2: branch-free (e^{2y}-1)/(e^{2y}+1); tiny-|y| passthrough select
__device__ __forceinline__ void tanh_s2_pair(float& a, float& b) {
    const float ya = a, yb = b;
    float2 s = unpack2(mul2(pack2(ya, yb), pack2(2.8853900817779268f, 2.8853900817779268f)));
    float ea, eb;
    asm("ex2.approx.ftz.f32 %0, %1;" : "=f"(ea) : "f"(s.x));
    asm("ex2.approx.ftz.f32 %0, %1;" : "=f"(eb) : "f"(s.y));
    float na = ea - 1.0f, da = ea + 1.0f;
    float nb = eb - 1.0f, db = eb + 1.0f;
    float ra, rb;
    asm("rcp.approx.ftz.f32 %0, %1;" : "=f"(ra) : "f"(da));
    asm("rcp.approx.ftz.f32 %0, %1;" : "=f"(rb) : "f"(db));
    float ta = na * ra;
    float tb = nb * rb;
    a = (fabsf(ya) >= 0.01f) ? ta : ya;
    b = (fabsf(yb) >= 0.01f) ? tb : yb;
}

__device__ __forceinline__ void tanh4_pair(float& a, float& b, const u64* __restrict__ C) {
    tanh_s1_pair(a, b);
    tanh_s2_pair(a, b);
    float2 f = unpack2(poly2(pack2(a, b), C)); a = f.x; b = f.y;
    f = unpack2(poly2(pack2(a, b), C));        a = f.x; b = f.y;
}

// =================== tanh kernel: 32 elems/thread ===================
#define TTPB 256
#define TANH_GRID (X_ELEMS / 32 / TTPB)   // 2048 blocks

__global__ void __launch_bounds__(TTPB)
tanh_kernel(const float4* __restrict__ xin, float4* __restrict__ xout)
{
    u64 C[8];
    make_coeffs(C);

    const int base = blockIdx.x * (TTPB * 8) + threadIdx.x;
    #pragma unroll
    for (int half = 0; half < 2; half++) {
        float4 v[4];
        #pragma unroll
        for (int k = 0; k < 4; k++) v[k] = xin[base + (half * 4 + k) * TTPB];
        #pragma unroll
        for (int k = 0; k < 4; k++) {
            tanh4_pair(v[k].x, v[k].y, C);
            tanh4_pair(v[k].z, v[k].w, C);
        }
        #pragma unroll
        for (int k = 0; k < 4; k++) xout[base + (half * 4 + k) * TTPB] = v[k];
    }
}

// =================== states kernel: 1 neuron/thread, 64-thread blocks ===================
#define STPB 64

// compare-exchange, descending (hi to lower index)
#define CE(arr, i, j) { float _hi = fmaxf(arr[i], arr[j]); \
                        float _lo = fminf(arr[i], arr[j]); \
                        arr[i] = _hi; arr[j] = _lo; }

__global__ void __launch_bounds__(STPB, 7)   // 146-reg cap, 7 blocks = 14 warps/SM
states_kernel(const float* __restrict__ ns,
              const float* __restrict__ Wenc,
              const float* __restrict__ benc,
              const float* __restrict__ Wdec,
              const float* __restrict__ bdec,
              float* __restrict__ sout)
{
    __shared__ __align__(16) float sWenc[CDIM * NSTATES];  // [j][s]
    __shared__ __align__(16) float sWdec[NSTATES * CDIM];  // [s][j]
    __shared__ float sbenc[CDIM];
    __shared__ float sbdec[NSTATES];
    {
        const int t = threadIdx.x;
        #pragma unroll
        for (int i = 0; i < (CDIM * NSTATES) / STPB; i++) {
            sWenc[t + i * STPB] = Wenc[t + i * STPB];
            sWdec[t + i * STPB] = Wdec[t + i * STPB];
        }
        if (t < CDIM) sbenc[t] = benc[t];
        else if (t >= 32 && t < 32 + NSTATES) sbdec[t - 32] = bdec[t - 32];
    }
    __syncthreads();

    const int n = blockIdx.x * STPB + threadIdx.x;

    float st[NSTATES];
    float acc[NSTATES];
    {
        const float4* src = reinterpret_cast<const float4*>(ns) + (size_t)n * (NSTATES / 4);
        #pragma unroll
        for (int i = 0; i < NSTATES / 4; i++) {
            float4 v = src[i];
            st[4*i+0] = v.x; st[4*i+1] = v.y; st[4*i+2] = v.z; st[4*i+3] = v.w;
        }
        // layer-0 sparsity mask (no-op for later layers: survivors are 0 or >=0.05)
        #pragma unroll
        for (int s = 0; s < NSTATES; s++) {
            float v = st[s];
            st[s] = (fabsf(v) >= 0.01f) ? v : 0.0f;
            acc[s] = 0.0f;
        }
    }

    #pragma unroll 1
    for (int L = 0; L < 4; L++) {
        // 0.9 decay folded into the recency normalizer
        const float wscl = (L == 0) ? 0.9f
                         : (L == 1) ? (0.9f / 1.7f)
                         : (L == 2) ? (0.9f / 2.19f)
                         :            (0.9f / 2.533f);

        // recency running sum -> scaled average, packed pairs for the GEMMs
        u64 pst[NSTATES / 2];
        #pragma unroll
        for (int i = 0; i < NSTATES / 2; i++) {
            float a0 = fmaf(acc[2*i+0], 0.7f, st[2*i+0]);
            float a1 = fmaf(acc[2*i+1], 0.7f, st[2*i+1]);
            acc[2*i+0] = a0; acc[2*i+1] = a1;
            pst[i] = pack2(a0 * wscl, a1 * wscl);
        }

        // encoder: h = relu(st @ Wenc^T + benc); unroll 4 -> 4 indep FFMA2 chains
        float h[CDIM];
        #pragma unroll 4
        for (int j = 0; j < CDIM; j++) {
            const ulonglong2* w = reinterpret_cast<const ulonglong2*>(&sWenc[j * NSTATES]);
            u64 a2 = pack2(sbenc[j], 0.0f);
            #pragma unroll
            for (int k = 0; k < 8; k++) {
                ulonglong2 wv = w[k];
                a2 = fma2(pst[2*k+0], wv.x, a2);
                a2 = fma2(pst[2*k+1], wv.y, a2);
            }
            float2 f = unpack2(a2);
            h[j] = fmaxf(f.x + f.y, 0.0f);
        }

        u64 ph[CDIM / 2];
        #pragma unroll
        for (int i = 0; i < CDIM / 2; i++) ph[i] = pack2(h[2*i], h[2*i+1]);

        // decoder + importance threshold
        #pragma unroll 4
        for (int s = 0; s < NSTATES; s++) {
            const ulonglong2* w = reinterpret_cast<const ulonglong2*>(&sWdec[s * CDIM]);
            u64 a2 = pack2(sbdec[s], 0.0f);
            #pragma unroll
            for (int k = 0; k < 4; k++) {
                ulonglong2 wv = w[k];
                a2 = fma2(ph[2*k+0], wv.x, a2);
                a2 = fma2(ph[2*k+1], wv.y, a2);
            }
            float2 f = unpack2(a2);
            float a = f.x + f.y;
            st[s] = (fabsf(a) >= 0.05f) ? a : 0.0f;
        }

        // ---- exact 8th-largest of |st| via bitonic selection ----
        float v[NSTATES];
        #pragma unroll
        for (int i = 0; i < NSTATES; i++) v[i] = fabsf(st[i]);

        // Batcher odd-even sort-8 (descending), 19 CE per group of 8
        #pragma unroll
        for (int g = 0; g < 32; g += 8) {
            CE(v, g+0, g+1) CE(v, g+2, g+3) CE(v, g+4, g+5) CE(v, g+6, g+7)
            CE(v, g+0, g+2) CE(v, g+1, g+3) CE(v, g+4, g+6) CE(v, g+5, g+7)
            CE(v, g+1, g+2) CE(v, g+5, g+6)
            CE(v, g+0, g+4) CE(v, g+1, g+5) CE(v, g+2, g+6) CE(v, g+3, g+7)
            CE(v, g+2, g+4) CE(v, g+3, g+5)
            CE(v, g+1, g+2) CE(v, g+3, g+4) CE(v, g+5, g+6)
        }

        // top-8 of G0∪G1 (bitonic split) then sort desc
        float m[8];
        #pragma unroll
        for (int i = 0; i < 8; i++) m[i] = fmaxf(v[i], v[15 - i]);
        CE(m,0,4) CE(m,1,5) CE(m,2,6) CE(m,3,7)
        CE(m,0,2) CE(m,1,3) CE(m,4,6) CE(m,5,7)
        CE(m,0,1) CE(m,2,3) CE(m,4,5) CE(m,6,7)

        // top-8 of G2∪G3, sorted
        float q[8];
        #pragma unroll
        for (int i = 0; i < 8; i++) q[i] = fmaxf(v[16 + i], v[31 - i]);
        CE(q,0,4) CE(q,1,5) CE(q,2,6) CE(q,3,7)
        CE(q,0,2) CE(q,1,3) CE(q,4,6) CE(q,5,7)
        CE(q,0,1) CE(q,2,3) CE(q,4,5) CE(q,6,7)

        // kth = min of top-8 of (m ∪ q) = min_i max(m[i], q[7-i])
        float kth = fmaxf(m[0], q[7]);
        #pragma unroll
        for (int i = 1; i < 8; i++) kth = fminf(kth, fmaxf(m[i], q[7 - i]));

        #pragma unroll
        for (int s = 0; s < NSTATES; s++)
            st[s] = (fabsf(st[s]) >= kth) ? st[s] : 0.0f;
    }

    {
        float4* dst = reinterpret_cast<float4*>(sout) + (size_t)n * (NSTATES / 4);
        #pragma unroll
        for (int i = 0; i < NSTATES / 4; i++) {
            float4 v4;
            v4.x = st[4*i+0]; v4.y = st[4*i+1]; v4.z = st[4*i+2]; v4.w = st[4*i+3];
            dst[i] = v4;
        }
    }
}

extern "C" void kernel_launch(void* const* d_in, const int* in_sizes, int n_in,
                              void* d_out, int out_size) {
    const float* x    = (const float*)d_in[0];
    const float* ns   = (const float*)d_in[1];
    const float* Wenc = (const float*)d_in[2];
    const float* benc = (const float*)d_in[3];
    const float* Wdec = (const float*)d_in[4];
    const float* bdec = (const float*)d_in[5];

    float* out  = (float*)d_out;
    float* xout = nullptr;
    float* sout = nullptr;
    if (out_size >= X_ELEMS + S_ELEMS) { xout = out; sout = out + X_ELEMS; }
    else if (out_size == S_ELEMS)      { sout = out; }
    else                               { xout = out; }

    if (xout)
        tanh_kernel<<<TANH_GRID, TTPB>>>(reinterpret_cast<const float4*>(x),
                                         reinterpret_cast<float4*>(xout));
    if (sout)
        states_kernel<<<N_NEURONS / STPB, STPB>>>(ns, Wenc, benc, Wdec, bdec, sout);
}